// round 1
// baseline (speedup 1.0000x reference)
#include <cuda_runtime.h>
#include <math_constants.h>

#define BATCH 16
#define H 1024
#define W 1024
#define HW (H * W)
#define TOPKN 512
#define CAP 131072

// Scratch (static __device__ allocations are allowed; cudaMalloc is not)
static __device__ float g_resp[(size_t)BATCH * HW];
static __device__ unsigned int g_imgmax[BATCH];
static __device__ int g_candcount[BATCH];
static __device__ unsigned long long g_cands[BATCH][CAP];

// float -> order-preserving uint32
__device__ __forceinline__ unsigned int ford(float f) {
    unsigned int u = __float_as_uint(f);
    return (u & 0x80000000u) ? ~u : (u | 0x80000000u);
}
__device__ __forceinline__ float finv(unsigned int u) {
    u = (u & 0x80000000u) ? (u & 0x7fffffffu) : ~u;
    return __uint_as_float(u);
}

__global__ void reset_kernel() {
    int t = threadIdx.x;
    if (t < BATCH) { g_imgmax[t] = 0u; g_candcount[t] = 0; }
}

// ---------------------------------------------------------------------------
// K1: quantize + Sobel + 7x7 structure tensor (exact int) + Shi-Tomasi resp
//     32x32 output tile, halo 4 (1 sobel + 3 box). Also per-image max.
// ---------------------------------------------------------------------------
__global__ __launch_bounds__(256) void resp_kernel(const float* __restrict__ im) {
    const int b = blockIdx.z;
    const int tx0 = blockIdx.x * 32, ty0 = blockIdx.y * 32;
    __shared__ short simg[40][42];
    __shared__ short sgx[38][40];
    __shared__ short sgy[38][40];
    __shared__ int sha[38][33];
    __shared__ int shb[38][33];
    __shared__ int shc[38][33];
    __shared__ unsigned int swmax[8];
    const int t = threadIdx.x;
    const float* imb = im + (size_t)b * HW;

    for (int i = t; i < 40 * 40; i += 256) {
        int r = i / 40, c = i % 40;
        int yy = ty0 - 4 + r, xx = tx0 - 4 + c;
        short v = 0;
        if ((unsigned)yy < H && (unsigned)xx < W)
            v = (short)__float2int_rd(imb[yy * W + xx] * 255.0f);
        simg[r][c] = v;
    }
    __syncthreads();

    // Gradients for tile + box halo 3; zero outside image (conv output domain)
    for (int i = t; i < 38 * 38; i += 256) {
        int r = i / 38, c = i % 38;
        int yy = ty0 - 3 + r, xx = tx0 - 3 + c;
        short gx = 0, gy = 0;
        if ((unsigned)yy < H && (unsigned)xx < W) {
            int s00 = simg[r][c],     s01 = simg[r][c + 1],     s02 = simg[r][c + 2];
            int s10 = simg[r + 1][c],                           s12 = simg[r + 1][c + 2];
            int s20 = simg[r + 2][c], s21 = simg[r + 2][c + 1], s22 = simg[r + 2][c + 2];
            gx = (short)((s02 - s00) + 2 * (s12 - s10) + (s22 - s20));
            gy = (short)((s20 - s00) + 2 * (s21 - s01) + (s22 - s02));
        }
        sgx[r][c] = gx; sgy[r][c] = gy;
    }
    __syncthreads();

    // Horizontal 7-sums of Ix^2, Ix*Iy, Iy^2 (exact int32)
    for (int i = t; i < 38 * 32; i += 256) {
        int r = i / 32, c = i % 32;
        int A = 0, Bv = 0, C = 0;
#pragma unroll
        for (int d = 0; d < 7; ++d) {
            int gx = sgx[r][c + d], gy = sgy[r][c + d];
            A += gx * gx; C += gy * gy; Bv += gx * gy;
        }
        sha[r][c] = A; shb[r][c] = Bv; shc[r][c] = C;
    }
    __syncthreads();

    unsigned int mloc = 0;
    for (int i = t; i < 32 * 32; i += 256) {
        int r = i / 32, c = i % 32;
        int A = 0, Bv = 0, C = 0;
#pragma unroll
        for (int d = 0; d < 7; ++d) { A += sha[r + d][c]; Bv += shb[r + d][c]; C += shc[r + d][c]; }
        float fa = (float)A, fc = (float)C, fb = (float)Bv;
        float dd = __fsub_rn(fa, fc);
        float s  = __fadd_rn(__fmul_rn(dd, dd), __fmul_rn(__fmul_rn(4.0f, fb), fb));
        float resp = 0.5f * __fsub_rn(__fadd_rn(fa, fc), __fsqrt_rn(s));
        g_resp[(size_t)b * HW + (size_t)(ty0 + r) * W + (tx0 + c)] = resp;
        unsigned int k = ford(resp);
        if (k > mloc) mloc = k;
    }
#pragma unroll
    for (int o = 16; o; o >>= 1) {
        unsigned int v = __shfl_xor_sync(0xffffffffu, mloc, o);
        if (v > mloc) mloc = v;
    }
    if ((t & 31) == 0) swmax[t >> 5] = mloc;
    __syncthreads();
    if (t == 0) {
        unsigned int m = swmax[0];
#pragma unroll
        for (int w = 1; w < 8; ++w) if (swmax[w] > m) m = swmax[w];
        atomicMax(&g_imgmax[b], m);
    }
}

// ---------------------------------------------------------------------------
// K2: 15x15 separable local max + threshold -> candidate keys
// ---------------------------------------------------------------------------
__global__ __launch_bounds__(256) void nms_kernel() {
    const int b = blockIdx.z;
    const int tx0 = blockIdx.x * 32, ty0 = blockIdx.y * 32;
    __shared__ float sr[46][48];
    __shared__ float sh[46][33];
    const int t = threadIdx.x;
    const float* rb = g_resp + (size_t)b * HW;

    for (int i = t; i < 46 * 46; i += 256) {
        int r = i / 46, c = i % 46;
        int yy = ty0 - 7 + r, xx = tx0 - 7 + c;
        sr[r][c] = ((unsigned)yy < H && (unsigned)xx < W) ? rb[yy * W + xx] : -CUDART_INF_F;
    }
    __syncthreads();

    for (int i = t; i < 46 * 32; i += 256) {
        int r = i / 32, c = i % 32;
        float m = sr[r][c];
#pragma unroll
        for (int d = 1; d < 15; ++d) m = fmaxf(m, sr[r][c + d]);
        sh[r][c] = m;
    }
    __syncthreads();

    const float thresh = 0.3f * finv(g_imgmax[b]);
    for (int i = t; i < 1024; i += 256) {
        int r = i / 32, c = i % 32;
        float m = sh[r][c];
#pragma unroll
        for (int d = 1; d < 15; ++d) m = fmaxf(m, sh[r + d][c]);
        float v = sr[r + 7][c + 7];
        if (v >= m && v >= thresh) {
            unsigned int idx = (unsigned)((ty0 + r) * W + (tx0 + c));
            unsigned long long key =
                ((unsigned long long)ford(v) << 32) | (unsigned int)(~idx);
            int slot = atomicAdd(&g_candcount[b], 1);
            if (slot < CAP) g_cands[b][slot] = key;
        }
    }
}

// ---------------------------------------------------------------------------
// K3: per-image exact top-512 by (value desc, idx asc) via 64-bit bitwise
//     radix-select, then bitonic sort 512, scatter mask + write coords.
// ---------------------------------------------------------------------------
__global__ __launch_bounds__(512) void topk_kernel(float* __restrict__ out, int write_coords) {
    const int b = blockIdx.x;
    const int t = threadIdx.x;
    __shared__ unsigned long long skeys[TOPKN];
    __shared__ int s_total;
    __shared__ int s_cnt;

    int n = g_candcount[b]; if (n > CAP) n = CAP;
    int Kb = n < TOPKN ? n : TOPKN;
    const unsigned long long* cb = g_cands[b];

    unsigned long long T = 0ull;
    if (Kb > 0) {
        for (int bit = 63; bit >= 0; --bit) {
            unsigned long long tryv = T | (1ull << bit);
            if (t == 0) s_total = 0;
            __syncthreads();
            int cnt = 0;
            for (int i = t; i < n; i += 512) cnt += (cb[i] >= tryv) ? 1 : 0;
#pragma unroll
            for (int o = 16; o; o >>= 1) cnt += __shfl_xor_sync(0xffffffffu, cnt, o);
            if ((t & 31) == 0) atomicAdd(&s_total, cnt);
            __syncthreads();
            if (s_total >= Kb) T = tryv;
            __syncthreads();
        }
    }

    if (t == 0) s_cnt = 0;
    __syncthreads();
    if (Kb > 0) {
        for (int i = t; i < n; i += 512) {
            unsigned long long k = cb[i];
            if (k >= T) {
                int p = atomicAdd(&s_cnt, 1);
                if (p < TOPKN) skeys[p] = k;
            }
        }
    }
    __syncthreads();
    int m = s_cnt < TOPKN ? s_cnt : TOPKN;
    if (t >= m) skeys[t] = 0ull;
    __syncthreads();

    // Bitonic sort, descending
    for (int k = 2; k <= TOPKN; k <<= 1) {
        for (int j = k >> 1; j > 0; j >>= 1) {
            int ixj = t ^ j;
            if (ixj > t) {
                unsigned long long a = skeys[t], c = skeys[ixj];
                bool sw = ((t & k) == 0) ? (a < c) : (a > c);
                if (sw) { skeys[t] = c; skeys[ixj] = a; }
            }
            __syncthreads();
        }
    }

    unsigned long long key = skeys[t];
    if (key != 0ull) {
        unsigned int idx = ~((unsigned int)key);
        out[(size_t)b * HW + idx] = 1.0f;
        if (write_coords) {
            float* coords = out + (size_t)BATCH * HW;
            coords[((size_t)b * TOPKN + t) * 2 + 0] = (float)(idx >> 10);
            coords[((size_t)b * TOPKN + t) * 2 + 1] = (float)(idx & 1023u);
        }
    } else if (write_coords) {
        float* coords = out + (size_t)BATCH * HW;
        coords[((size_t)b * TOPKN + t) * 2 + 0] = -1.0f;
        coords[((size_t)b * TOPKN + t) * 2 + 1] = -1.0f;
    }
}

extern "C" void kernel_launch(void* const* d_in, const int* in_sizes, int n_in,
                              void* d_out, int out_size) {
    const float* im = (const float*)d_in[0];
    float* out = (float*)d_out;

    cudaMemsetAsync(d_out, 0, (size_t)out_size * sizeof(float));
    reset_kernel<<<1, 32>>>();

    dim3 grid(W / 32, H / 32, BATCH);
    resp_kernel<<<grid, 256>>>(im);
    nms_kernel<<<grid, 256>>>();

    int wc = (out_size >= BATCH * HW + BATCH * TOPKN * 2) ? 1 : 0;
    topk_kernel<<<BATCH, 512>>>(out, wc);
}